// round 2
// baseline (speedup 1.0000x reference)
#include <cuda_runtime.h>
#include <math.h>
#include <stdint.h>

#define N_NODES 30000
#define N_EDGES 300000
#define N_GRAPHS 256
#define DD 128
#define HH 256
#define NLAYERS 3

#define FLAG_RELU 1
#define FLAG_ADDC 2

// ---------------- scratch (static device allocations; no cudaMalloc) -------
__device__ float g_h[N_NODES * DD];              // node state
__device__ float g_E[(size_t)N_EDGES * 512];     // [Em(256) | Er(256)] per edge (b1 folded in)
__device__ float g_PQ[N_NODES * 1024];           // [Pm|Qm|Pr|Qr] per node
__device__ float g_S[N_NODES * 512];             // [segsum hid_m | segsum hid_r]
__device__ float g_X[N_NODES * 384];             // [agg | ragg | h]
__device__ float g_Hu[N_NODES * HH];             // upd hidden; reused for final gate input g
__device__ float g_gv[N_GRAPHS * DD];
__device__ float g_gv2[N_GRAPHS * DD];
__device__ int   g_degt[N_NODES];
__device__ int   g_degf[N_NODES];
__device__ float g_WE[16 * 512];                 // folded edge-feature weights
__device__ float g_c[512];                       // folded edge bias
__device__ float g_Wcat[128 * 1024];             // [W1m[0:128]|W1m[128:256]|W1r[0:128]|W1r[128:256]]

// ---------------- helpers ---------------------------------------------------
__device__ __forceinline__ void red_add_v4(float* addr, float4 v) {
    asm volatile("red.global.add.v4.f32 [%0], {%1,%2,%3,%4};"
                 :: "l"(addr), "f"(v.x), "f"(v.y), "f"(v.z), "f"(v.w) : "memory");
}

// packed fp32x2 FMA (Blackwell): d = a*b + d, per 32-bit lane, rn — bit-identical to fmaf
#define FMA2(d, a, b) asm("fma.rn.f32x2 %0, %1, %2, %0;" : "+l"(d) : "l"(a), "l"(b))

__global__ void zero_k(float4* p, int n4) {
    int i = blockIdx.x * 256 + threadIdx.x;
    if (i < n4) p[i] = make_float4(0.f, 0.f, 0.f, 0.f);
}

// ---------------- weight folding --------------------------------------------
__global__ void fold_k(const float* __restrict__ enc_we, const float* __restrict__ enc_be,
                       const float* __restrict__ mw1, const float* __restrict__ mb1,
                       const float* __restrict__ rw1, const float* __restrict__ rb1) {
    int j = threadIdx.x;                       // 0..511
    const float* W1 = (j < 256) ? mw1 : rw1;
    const float* b1 = (j < 256) ? mb1 : rb1;
    int jc = j & 255;
    for (int k = 0; k < 16; k++) {
        float acc = 0.f;
        for (int d = 0; d < 128; d++)
            acc = fmaf(enc_we[k * 128 + d], W1[(256 + d) * 256 + jc], acc);
        g_WE[k * 512 + j] = acc;
    }
    float acc = b1[jc];
    for (int d = 0; d < 128; d++)
        acc = fmaf(enc_be[d], W1[(256 + d) * 256 + jc], acc);
    g_c[j] = acc;
}

__global__ void wcat_k(const float* __restrict__ mw1, const float* __restrict__ rw1) {
    int idx = blockIdx.x * 256 + threadIdx.x;   // 128*1024
    if (idx >= 128 * 1024) return;
    int d = idx >> 10, c = idx & 1023;
    float v;
    if      (c < 256) v = mw1[d * 256 + c];
    else if (c < 512) v = mw1[(128 + d) * 256 + (c - 256)];
    else if (c < 768) v = rw1[d * 256 + (c - 512)];
    else              v = rw1[(128 + d) * 256 + (c - 768)];
    g_Wcat[idx] = v;
}

// ---------------- degree histogram -----------------------------------------
__global__ void hist_k(const int* __restrict__ from, const int* __restrict__ to) {
    int i = blockIdx.x * 256 + threadIdx.x;
    if (i >= N_EDGES) return;
    atomicAdd(&g_degt[to[i]], 1);
    atomicAdd(&g_degf[from[i]], 1);
}

// ---------------- FFMA2 SGEMM:  C = [C +] relu( A@B + rowScale*bias ) -------
// 128x128 tile, 256 threads, 8x8 per thread held as 8x4 packed-f32x2 accumulators.
// A fragment stored DUPLICATED in SMEM so vector loads give (a,a) pairs directly.
#define ASTR 264   // floats per As2 row (256 payload + 8 pad)

__global__ void __launch_bounds__(256, 2) sgemm_k(
    const float* __restrict__ A, int lda,
    const float* __restrict__ B, int ldb,
    const float* __restrict__ bias,
    const int* __restrict__ rowScale,
    float* __restrict__ C, int ldc,
    int M, int N, int K, int flags)
{
    __shared__ __align__(16) float As2[16 * ASTR];   // [k][2*m] duplicated
    __shared__ __align__(16) float Bs[16 * 128];     // [k][n]
    const int tid = threadIdx.x;
    const int m0 = blockIdx.x * 128;
    const int n0 = blockIdx.y * 128;
    const int tx = tid & 15;
    const int ty = tid >> 4;

    unsigned long long acc[32];
    #pragma unroll
    for (int i = 0; i < 32; i++) acc[i] = 0ull;

    const int aRow = tid >> 2;           // 0..63
    const int aCol = (tid & 3) << 2;     // 0,4,8,12
    const int bRow = tid >> 5;           // 0..7
    const int bCol = (tid & 31) << 2;

    for (int k0 = 0; k0 < K; k0 += 16) {
        #pragma unroll
        for (int hh = 0; hh < 2; hh++) {
            int mloc = aRow + hh * 64;
            int m = m0 + mloc;
            float4 av = make_float4(0.f, 0.f, 0.f, 0.f);
            if (m < M) av = *(const float4*)(A + (size_t)m * lda + k0 + aCol);
            int mm = mloc * 2;
            *(float2*)(&As2[(aCol + 0) * ASTR + mm]) = make_float2(av.x, av.x);
            *(float2*)(&As2[(aCol + 1) * ASTR + mm]) = make_float2(av.y, av.y);
            *(float2*)(&As2[(aCol + 2) * ASTR + mm]) = make_float2(av.z, av.z);
            *(float2*)(&As2[(aCol + 3) * ASTR + mm]) = make_float2(av.w, av.w);
        }
        #pragma unroll
        for (int hh = 0; hh < 2; hh++) {
            int kk = bRow + hh * 8;
            *(float4*)(&Bs[kk * 128 + bCol]) = *(const float4*)(B + (size_t)(k0 + kk) * ldb + n0 + bCol);
        }
        __syncthreads();
        #pragma unroll
        for (int kk = 0; kk < 16; kk++) {
            const float* aB = As2 + kk * ASTR + ty * 16;
            const float* bB = Bs + kk * 128 + tx * 8;
            ulonglong2 a0 = *(const ulonglong2*)(aB + 0);
            ulonglong2 a1 = *(const ulonglong2*)(aB + 4);
            ulonglong2 a2 = *(const ulonglong2*)(aB + 8);
            ulonglong2 a3 = *(const ulonglong2*)(aB + 12);
            ulonglong2 b0 = *(const ulonglong2*)(bB + 0);
            ulonglong2 b1 = *(const ulonglong2*)(bB + 4);
            unsigned long long av[8] = {a0.x, a0.y, a1.x, a1.y, a2.x, a2.y, a3.x, a3.y};
            unsigned long long bv[4] = {b0.x, b0.y, b1.x, b1.y};
            #pragma unroll
            for (int i = 0; i < 8; i++) {
                #pragma unroll
                for (int j = 0; j < 4; j++)
                    FMA2(acc[i * 4 + j], av[i], bv[j]);
            }
        }
        __syncthreads();
    }

    #pragma unroll
    for (int i = 0; i < 8; i++) {
        int m = m0 + ty * 8 + i;
        if (m >= M) continue;
        float rs = rowScale ? (float)rowScale[m] : 1.f;
        #pragma unroll
        for (int h = 0; h < 2; h++) {
            union { unsigned long long u; float2 f; } p0, p1;
            p0.u = acc[i * 4 + 2 * h];
            p1.u = acc[i * 4 + 2 * h + 1];
            float4 v = make_float4(p0.f.x, p0.f.y, p1.f.x, p1.f.y);
            int n = n0 + tx * 8 + 4 * h;
            if (bias) {
                v.x = fmaf(rs, bias[n + 0], v.x);
                v.y = fmaf(rs, bias[n + 1], v.y);
                v.z = fmaf(rs, bias[n + 2], v.z);
                v.w = fmaf(rs, bias[n + 3], v.w);
            }
            float* cp = C + (size_t)m * ldc + n;
            if (flags & FLAG_ADDC) {
                float4 c0 = *(const float4*)cp;
                v.x += c0.x; v.y += c0.y; v.z += c0.z; v.w += c0.w;
            }
            if (flags & FLAG_RELU) {
                v.x = fmaxf(v.x, 0.f); v.y = fmaxf(v.y, 0.f);
                v.z = fmaxf(v.z, 0.f); v.w = fmaxf(v.w, 0.f);
            }
            *(float4*)cp = v;
        }
    }
}

// ---------------- per-edge elementwise pass (one warp per edge) -------------
__global__ void edge_pass_k(const int* __restrict__ from, const int* __restrict__ to) {
    int warp = (blockIdx.x * 256 + threadIdx.x) >> 5;
    int lane = threadIdx.x & 31;
    if (warp >= N_EDGES) return;
    int f = from[warp], t = to[warp];
    const float4* E4 = (const float4*)(g_E + (size_t)warp * 512);
    const float4* Pf = (const float4*)(g_PQ + (size_t)f * 1024);
    const float4* Pt = (const float4*)(g_PQ + (size_t)t * 1024);
    float* Sm = g_S + (size_t)t * 512;
    float* Sr = g_S + (size_t)f * 512 + 256;
    #pragma unroll
    for (int s = 0; s < 2; s++) {
        int c = lane + 32 * s;                 // float4 column index 0..63
        float4 e = E4[c], a = Pf[c], b = Pt[64 + c];
        float4 v;
        v.x = fmaxf(e.x + a.x + b.x, 0.f);
        v.y = fmaxf(e.y + a.y + b.y, 0.f);
        v.z = fmaxf(e.z + a.z + b.z, 0.f);
        v.w = fmaxf(e.w + a.w + b.w, 0.f);
        red_add_v4(Sm + 4 * c, v);
        float4 e2 = E4[64 + c], a2 = Pt[128 + c], b2 = Pf[192 + c];
        float4 v2;
        v2.x = fmaxf(e2.x + a2.x + b2.x, 0.f);
        v2.y = fmaxf(e2.y + a2.y + b2.y, 0.f);
        v2.z = fmaxf(e2.z + a2.z + b2.z, 0.f);
        v2.w = fmaxf(e2.w + a2.w + b2.w, 0.f);
        red_add_v4(Sr + 4 * c, v2);
    }
}

// copy h into X[:, 256:384]
__global__ void copyh_k() {
    int idx = blockIdx.x * 256 + threadIdx.x;   // N_NODES*32 float4
    if (idx >= N_NODES * 32) return;
    int n = idx >> 5, c = idx & 31;
    ((float4*)(g_X + (size_t)n * 384 + 256))[c] = ((const float4*)(g_h + (size_t)n * 128))[c];
}

// gated graph pooling: gv[graph] += sigmoid(g[:, :128]) * g[:, 128:]
__global__ void gate_k(const int* __restrict__ gidx) {
    int idx = blockIdx.x * 256 + threadIdx.x;   // N_NODES*32
    if (idx >= N_NODES * 32) return;
    int n = idx >> 5, c4 = (idx & 31) * 4;
    const float* gr = g_Hu + (size_t)n * 256;
    float4 a = *(const float4*)&gr[c4];
    float4 b = *(const float4*)&gr[128 + c4];
    float4 v;
    v.x = b.x / (1.f + expf(-a.x));
    v.y = b.y / (1.f + expf(-a.y));
    v.z = b.z / (1.f + expf(-a.z));
    v.w = b.w / (1.f + expf(-a.w));
    red_add_v4(&g_gv[gidx[n] * 128 + c4], v);
}

__global__ void gv2_k(const float* __restrict__ W, const float* __restrict__ b) {
    __shared__ float row[128];
    int r = blockIdx.x, d = threadIdx.x;        // 256 x 128
    row[d] = g_gv[r * 128 + d];
    __syncthreads();
    float acc = b[d];
    #pragma unroll 8
    for (int k = 0; k < 128; k++) acc = fmaf(row[k], W[k * 128 + d], acc);
    g_gv2[r * 128 + d] = acc;
}

__global__ void out_k(float* __restrict__ out) {
    __shared__ float sdata[128];
    int p = blockIdx.x, t = threadIdx.x;        // 128 x 128
    float dxy = g_gv2[(2 * p) * 128 + t] - g_gv2[(2 * p + 1) * 128 + t];
    sdata[t] = dxy * dxy;
    __syncthreads();
    for (int s = 64; s > 0; s >>= 1) {
        if (t < s) sdata[t] += sdata[t + s];
        __syncthreads();
    }
    if (t == 0) out[p] = -sdata[0];
}

// ---------------- host launch ----------------------------------------------
static void* sym(const void* s) { void* p = nullptr; cudaGetSymbolAddress(&p, s); return p; }

extern "C" void kernel_launch(void* const* d_in, const int* in_sizes, int n_in,
                              void* d_out, int out_size) {
    const float* nf     = (const float*)d_in[0];
    const float* ef     = (const float*)d_in[1];
    const int*   from   = (const int*)d_in[2];
    const int*   to     = (const int*)d_in[3];
    const int*   gidx   = (const int*)d_in[4];
    const float* enc_wn = (const float*)d_in[5];
    const float* enc_bn = (const float*)d_in[6];
    const float* enc_we = (const float*)d_in[7];
    const float* enc_be = (const float*)d_in[8];
    const float* msg_w1 = (const float*)d_in[9];
    const float* msg_b1 = (const float*)d_in[10];
    const float* msg_w2 = (const float*)d_in[11];
    const float* msg_b2 = (const float*)d_in[12];
    const float* rmsg_w1= (const float*)d_in[13];
    const float* rmsg_b1= (const float*)d_in[14];
    const float* rmsg_w2= (const float*)d_in[15];
    const float* rmsg_b2= (const float*)d_in[16];
    const float* upd_w1 = (const float*)d_in[17];
    const float* upd_b1 = (const float*)d_in[18];
    const float* upd_w2 = (const float*)d_in[19];
    const float* upd_b2 = (const float*)d_in[20];
    const float* agg_w1 = (const float*)d_in[21];
    const float* agg_b1 = (const float*)d_in[22];
    const float* agg_w2 = (const float*)d_in[23];
    const float* agg_b2 = (const float*)d_in[24];
    float* out = (float*)d_out;

    float* p_h    = (float*)sym(g_h);
    float* p_E    = (float*)sym(g_E);
    float* p_PQ   = (float*)sym(g_PQ);
    float* p_S    = (float*)sym(g_S);
    float* p_X    = (float*)sym(g_X);
    float* p_Hu   = (float*)sym(g_Hu);
    float* p_gv   = (float*)sym(g_gv);
    float* p_Wcat = (float*)sym(g_Wcat);
    float* p_WE   = (float*)sym(g_WE);
    float* p_c    = (float*)sym(g_c);
    int*   p_degt = (int*)sym(g_degt);
    int*   p_degf = (int*)sym(g_degf);

    const int GM = (N_NODES + 127) / 128;   // 235
    const int GE = (N_EDGES + 127) / 128;   // 2344

    // one-time prep
    fold_k<<<1, 512>>>(enc_we, enc_be, msg_w1, msg_b1, rmsg_w1, rmsg_b1);
    wcat_k<<<512, 256>>>(msg_w1, rmsg_w1);
    zero_k<<<(N_NODES / 4 + 255) / 256, 256>>>((float4*)p_degt, N_NODES / 4);
    zero_k<<<(N_NODES / 4 + 255) / 256, 256>>>((float4*)p_degf, N_NODES / 4);
    hist_k<<<(N_EDGES + 255) / 256, 256>>>(from, to);
    // node encoder: h = nf @ enc_wn + enc_bn           [30000,32]@[32,128]
    sgemm_k<<<dim3(GM, 1), 256>>>(nf, 32, enc_wn, 128, enc_bn, nullptr,
                                  p_h, 128, N_NODES, 128, 32, 0);
    // edge encoder (folded): E = ef @ WE + c           [300000,16]@[16,512]
    sgemm_k<<<dim3(GE, 4), 256>>>(ef, 16, p_WE, 512, p_c, nullptr,
                                  p_E, 512, N_EDGES, 512, 16, 0);

    for (int l = 0; l < NLAYERS; l++) {
        // PQ = h @ Wcat                                [30000,128]@[128,1024]
        sgemm_k<<<dim3(GM, 8), 256>>>(p_h, 128, p_Wcat, 1024, nullptr, nullptr,
                                      p_PQ, 1024, N_NODES, 1024, 128, 0);
        zero_k<<<(N_NODES * 128 + 255) / 256, 256>>>((float4*)p_S, N_NODES * 128);
        edge_pass_k<<<N_EDGES / 8, 256>>>(from, to);
        // agg  = S[:, :256] @ msg_w2  + deg_to  * msg_b2   -> X[:, 0:128]
        sgemm_k<<<dim3(GM, 1), 256>>>(p_S, 512, msg_w2, 128, msg_b2, p_degt,
                                      p_X, 384, N_NODES, 128, 256, 0);
        // ragg = S[:, 256:] @ rmsg_w2 + deg_from * rmsg_b2 -> X[:, 128:256]
        sgemm_k<<<dim3(GM, 1), 256>>>(p_S + 256, 512, rmsg_w2, 128, rmsg_b2, p_degf,
                                      p_X + 128, 384, N_NODES, 128, 256, 0);
        copyh_k<<<(N_NODES * 32 + 255) / 256, 256>>>();
        // Hu = relu(X @ upd_w1 + b1)                   [30000,384]@[384,256]
        sgemm_k<<<dim3(GM, 2), 256>>>(p_X, 384, upd_w1, 256, upd_b1, nullptr,
                                      p_Hu, 256, N_NODES, 256, 384, FLAG_RELU);
        // h += Hu @ upd_w2 + b2                        [30000,256]@[256,128]
        sgemm_k<<<dim3(GM, 1), 256>>>(p_Hu, 256, upd_w2, 128, upd_b2, nullptr,
                                      p_h, 128, N_NODES, 128, 256, FLAG_ADDC);
    }

    // g = h @ agg_w1 + b1  (into g_Hu, [30000,256])
    sgemm_k<<<dim3(GM, 2), 256>>>(p_h, 128, agg_w1, 256, agg_b1, nullptr,
                                  p_Hu, 256, N_NODES, 256, 128, 0);
    zero_k<<<(N_GRAPHS * 32 + 255) / 256, 256>>>((float4*)p_gv, N_GRAPHS * 32);
    gate_k<<<(N_NODES * 32 + 255) / 256, 256>>>(gidx);
    gv2_k<<<N_GRAPHS, 128>>>(agg_w2, agg_b2);
    out_k<<<128, 128>>>(out);
    (void)in_sizes; (void)n_in; (void)out_size;
}

// round 4
// speedup vs baseline: 1.4899x; 1.4899x over previous
#include <cuda_runtime.h>
#include <cuda_bf16.h>
#include <math.h>
#include <stdint.h>

#define N_NODES 30000
#define N_EDGES 300000
#define N_GRAPHS 256
#define DD 128
#define HH 256
#define NLAYERS 3

#define FLAG_RELU 1
#define FLAG_ADDC 2

// ---------------- scratch -------------------------------------------------
__device__ float g_h[N_NODES * DD];
__device__ float g_E[(size_t)N_EDGES * 512];
__device__ float g_PQ[N_NODES * 1024];
__device__ float g_S[N_NODES * 512];
__device__ float g_X[N_NODES * 384];
__device__ float g_Hu[N_NODES * HH];
__device__ float g_gv[N_GRAPHS * DD];
__device__ float g_gv2[N_GRAPHS * DD];
__device__ int   g_degt[N_NODES];
__device__ int   g_degf[N_NODES];
__device__ float g_WE[16 * 512];
__device__ float g_c[512];
__device__ float g_Wcat[128 * 1024];

// bf16 hi/lo weight pool, [N][K] K-major (transposed)
#define OFF_CAT 0
#define OFF_MW2 131072
#define OFF_RW2 163840
#define OFF_UW1 196608
#define OFF_UW2 294912
#define OFF_AW1 327680
#define OFF_ENW 360448
#define OFF_WET 364544
#define BPOOL   372736
__device__ __nv_bfloat16 g_Bh[BPOOL];
__device__ __nv_bfloat16 g_Bl[BPOOL];

// ---------------- helpers ---------------------------------------------------
__device__ __forceinline__ void red_add_v4(float* addr, float4 v) {
    asm volatile("red.global.add.v4.f32 [%0], {%1,%2,%3,%4};"
                 :: "l"(addr), "f"(v.x), "f"(v.y), "f"(v.z), "f"(v.w) : "memory");
}
__device__ __forceinline__ uint32_t packlo2(float a, float b) {
    uint32_t r;
    asm("cvt.rn.bf16x2.f32 %0, %1, %2;" : "=r"(r) : "f"(b), "f"(a));  // hi half = b
    return r;
}
__device__ __forceinline__ void mma16816(float* c, const uint32_t* a, const uint32_t* b) {
    asm volatile("mma.sync.aligned.m16n8k16.row.col.f32.bf16.bf16.f32 "
                 "{%0,%1,%2,%3}, {%4,%5,%6,%7}, {%8,%9}, {%0,%1,%2,%3};"
                 : "+f"(c[0]), "+f"(c[1]), "+f"(c[2]), "+f"(c[3])
                 : "r"(a[0]), "r"(a[1]), "r"(a[2]), "r"(a[3]), "r"(b[0]), "r"(b[1]));
}

__global__ void zero_k(float4* p, int n4) {
    int i = blockIdx.x * 256 + threadIdx.x;
    if (i < n4) p[i] = make_float4(0.f, 0.f, 0.f, 0.f);
}

// ---------------- warp-MMA split-bf16 GEMM ----------------------------------
// C[M,N] = [C +] relu( A[M,K](f32) @ B[N,K]^T + rowScale*bias )
#define AST 20   // smem row stride in 32-bit words (32 bf16 payload + 8 pad)

__global__ void __launch_bounds__(256) tgemm_k(
    const float* __restrict__ A, int lda, int K,
    const __nv_bfloat16* __restrict__ Bh, const __nv_bfloat16* __restrict__ Bl,
    const float* __restrict__ bias, const int* __restrict__ rowScale,
    float* __restrict__ C, int ldc, int M, int N, int flags)
{
    __shared__ uint32_t sAh[128 * AST], sAl[128 * AST];
    __shared__ uint32_t sBh[128 * AST], sBl[128 * AST];
    const int tid = threadIdx.x, wid = tid >> 5, lane = tid & 31;
    const int g = lane >> 2, t = lane & 3;
    const int m0 = blockIdx.x * 128, n0 = blockIdx.y * 128;
    const int mbase = (wid & 3) * 32, nbase = (wid >> 2) * 64;

    float acc[2][8][4];
    #pragma unroll
    for (int i = 0; i < 2; i++)
        #pragma unroll
        for (int j = 0; j < 8; j++)
            #pragma unroll
            for (int q = 0; q < 4; q++) acc[i][j][q] = 0.f;

    const int arow = tid >> 1, ahalf = tid & 1;
    const bool mok = (m0 + arow) < M;
    const float* Ap = A + (size_t)(m0 + arow) * lda;
    const __nv_bfloat16* Bhp = Bh + (size_t)(n0 + arow) * K;
    const __nv_bfloat16* Blp = Bl + (size_t)(n0 + arow) * K;

    for (int k0 = 0; k0 < K; k0 += 32) {
        // ---- A: load f32, truncation-split to bf16 hi/lo, pack to smem ----
        {
            const bool kok = (k0 + ahalf * 16) < K;
            #pragma unroll
            for (int j = 0; j < 4; j++) {
                int c = ahalf * 16 + j * 4;
                float4 v = make_float4(0.f, 0.f, 0.f, 0.f);
                if (mok && kok) v = *(const float4*)(Ap + k0 + c);
                uint32_t x0 = __float_as_uint(v.x), x1 = __float_as_uint(v.y);
                uint32_t x2 = __float_as_uint(v.z), x3 = __float_as_uint(v.w);
                uint32_t hw0 = (x1 & 0xFFFF0000u) | (x0 >> 16);
                uint32_t hw1 = (x3 & 0xFFFF0000u) | (x2 >> 16);
                float l0 = v.x - __uint_as_float(x0 & 0xFFFF0000u);
                float l1 = v.y - __uint_as_float(x1 & 0xFFFF0000u);
                float l2 = v.z - __uint_as_float(x2 & 0xFFFF0000u);
                float l3 = v.w - __uint_as_float(x3 & 0xFFFF0000u);
                int w = arow * AST + (c >> 1);
                sAh[w] = hw0; sAh[w + 1] = hw1;
                sAl[w] = packlo2(l0, l1); sAl[w + 1] = packlo2(l2, l3);
            }
        }
        // ---- B: copy pre-split bf16 hi/lo to smem ----
        #pragma unroll
        for (int h2 = 0; h2 < 2; h2++) {
            int koff = ahalf * 16 + h2 * 8;
            int w = arow * AST + (koff >> 1);
            if (k0 + koff < K) {
                *(uint4*)&sBh[w] = *(const uint4*)(Bhp + k0 + koff);
                *(uint4*)&sBl[w] = *(const uint4*)(Blp + k0 + koff);
            } else {
                uint4 z = make_uint4(0, 0, 0, 0);
                *(uint4*)&sBh[w] = z;
                *(uint4*)&sBl[w] = z;
            }
        }
        __syncthreads();

        #pragma unroll
        for (int ks = 0; ks < 2; ks++) {
            const int wb = ks * 8 + t;
            uint32_t ah[2][4], al[2][4];
            #pragma unroll
            for (int i = 0; i < 2; i++) {
                int r0 = (mbase + 16 * i + g) * AST;
                int r8 = r0 + 8 * AST;
                ah[i][0] = sAh[r0 + wb]; ah[i][1] = sAh[r8 + wb];
                ah[i][2] = sAh[r0 + wb + 4]; ah[i][3] = sAh[r8 + wb + 4];
                al[i][0] = sAl[r0 + wb]; al[i][1] = sAl[r8 + wb];
                al[i][2] = sAl[r0 + wb + 4]; al[i][3] = sAl[r8 + wb + 4];
            }
            #pragma unroll
            for (int j = 0; j < 8; j++) {
                int rn = (nbase + 8 * j + g) * AST;
                uint32_t bh[2] = { sBh[rn + wb], sBh[rn + wb + 4] };
                uint32_t bl[2] = { sBl[rn + wb], sBl[rn + wb + 4] };
                #pragma unroll
                for (int i = 0; i < 2; i++) {
                    mma16816(acc[i][j], ah[i], bh);
                    mma16816(acc[i][j], al[i], bh);
                    mma16816(acc[i][j], ah[i], bl);
                }
            }
        }
        __syncthreads();
    }

    // ---- epilogue ----
    #pragma unroll
    for (int i = 0; i < 2; i++) {
        #pragma unroll
        for (int rr = 0; rr < 2; rr++) {
            int row = m0 + mbase + 16 * i + g + 8 * rr;
            if (row >= M) continue;
            float rs = rowScale ? (float)rowScale[row] : 1.f;
            float* crow = C + (size_t)row * ldc;
            #pragma unroll
            for (int j = 0; j < 8; j++) {
                int nn = n0 + nbase + 8 * j + 2 * t;
                float2 v = make_float2(acc[i][j][2 * rr], acc[i][j][2 * rr + 1]);
                if (bias) {
                    v.x = fmaf(rs, bias[nn], v.x);
                    v.y = fmaf(rs, bias[nn + 1], v.y);
                }
                if (flags & FLAG_ADDC) {
                    float2 c0 = *(const float2*)(crow + nn);
                    v.x += c0.x; v.y += c0.y;
                }
                if (flags & FLAG_RELU) {
                    v.x = fmaxf(v.x, 0.f); v.y = fmaxf(v.y, 0.f);
                }
                *(float2*)(crow + nn) = v;
            }
        }
    }
}

// ---------------- prep kernels ---------------------------------------------
// split + transpose: W[K][N] f32 -> Bh/Bl[N][K] bf16 (truncation split)
__global__ void spt_k(const float* __restrict__ W, __nv_bfloat16* __restrict__ oh,
                      __nv_bfloat16* __restrict__ ol, int K, int N) {
    int idx = blockIdx.x * 256 + threadIdx.x;
    if (idx >= K * N) return;
    int k = idx / N, n = idx % N;
    float v = W[idx];
    uint32_t xu = __float_as_uint(v);
    unsigned short hb = (unsigned short)(xu >> 16);
    float hf = __uint_as_float(xu & 0xFFFF0000u);
    __nv_bfloat16 l = __float2bfloat16(v - hf);
    union { unsigned short s; __nv_bfloat16 b; } u; u.s = hb;
    oh[(size_t)n * K + k] = u.b;
    ol[(size_t)n * K + k] = l;
}

__global__ void fold_k(const float* __restrict__ enc_we, const float* __restrict__ enc_be,
                       const float* __restrict__ mw1, const float* __restrict__ mb1,
                       const float* __restrict__ rw1, const float* __restrict__ rb1) {
    int j = threadIdx.x;
    const float* W1 = (j < 256) ? mw1 : rw1;
    const float* b1 = (j < 256) ? mb1 : rb1;
    int jc = j & 255;
    for (int k = 0; k < 16; k++) {
        float acc = 0.f;
        for (int d = 0; d < 128; d++)
            acc = fmaf(enc_we[k * 128 + d], W1[(256 + d) * 256 + jc], acc);
        g_WE[k * 512 + j] = acc;
    }
    float acc = b1[jc];
    for (int d = 0; d < 128; d++)
        acc = fmaf(enc_be[d], W1[(256 + d) * 256 + jc], acc);
    g_c[j] = acc;
}

__global__ void wcat_k(const float* __restrict__ mw1, const float* __restrict__ rw1) {
    int idx = blockIdx.x * 256 + threadIdx.x;
    if (idx >= 128 * 1024) return;
    int d = idx >> 10, c = idx & 1023;
    float v;
    if      (c < 256) v = mw1[d * 256 + c];
    else if (c < 512) v = mw1[(128 + d) * 256 + (c - 256)];
    else if (c < 768) v = rw1[d * 256 + (c - 512)];
    else              v = rw1[(128 + d) * 256 + (c - 768)];
    g_Wcat[idx] = v;
}

__global__ void hist_k(const int* __restrict__ from, const int* __restrict__ to) {
    int i = blockIdx.x * 256 + threadIdx.x;
    if (i >= N_EDGES) return;
    atomicAdd(&g_degt[to[i]], 1);
    atomicAdd(&g_degf[from[i]], 1);
}

// ---------------- per-edge elementwise pass ---------------------------------
__global__ void edge_pass_k(const int* __restrict__ from, const int* __restrict__ to) {
    int warp = (blockIdx.x * 256 + threadIdx.x) >> 5;
    int lane = threadIdx.x & 31;
    if (warp >= N_EDGES) return;
    int f = from[warp], t = to[warp];
    const float4* E4 = (const float4*)(g_E + (size_t)warp * 512);
    const float4* Pf = (const float4*)(g_PQ + (size_t)f * 1024);
    const float4* Pt = (const float4*)(g_PQ + (size_t)t * 1024);
    float* Sm = g_S + (size_t)t * 512;
    float* Sr = g_S + (size_t)f * 512 + 256;
    #pragma unroll
    for (int s = 0; s < 2; s++) {
        int c = lane + 32 * s;
        float4 e = E4[c], a = Pf[c], b = Pt[64 + c];
        float4 v;
        v.x = fmaxf(e.x + a.x + b.x, 0.f);
        v.y = fmaxf(e.y + a.y + b.y, 0.f);
        v.z = fmaxf(e.z + a.z + b.z, 0.f);
        v.w = fmaxf(e.w + a.w + b.w, 0.f);
        red_add_v4(Sm + 4 * c, v);
        float4 e2 = E4[64 + c], a2 = Pt[128 + c], b2 = Pf[192 + c];
        float4 v2;
        v2.x = fmaxf(e2.x + a2.x + b2.x, 0.f);
        v2.y = fmaxf(e2.y + a2.y + b2.y, 0.f);
        v2.z = fmaxf(e2.z + a2.z + b2.z, 0.f);
        v2.w = fmaxf(e2.w + a2.w + b2.w, 0.f);
        red_add_v4(Sr + 4 * c, v2);
    }
}

__global__ void copyh_k() {
    int idx = blockIdx.x * 256 + threadIdx.x;
    if (idx >= N_NODES * 32) return;
    int n = idx >> 5, c = idx & 31;
    ((float4*)(g_X + (size_t)n * 384 + 256))[c] = ((const float4*)(g_h + (size_t)n * 128))[c];
}

__global__ void gate_k(const int* __restrict__ gidx) {
    int idx = blockIdx.x * 256 + threadIdx.x;
    if (idx >= N_NODES * 32) return;
    int n = idx >> 5, c4 = (idx & 31) * 4;
    const float* gr = g_Hu + (size_t)n * 256;
    float4 a = *(const float4*)&gr[c4];
    float4 b = *(const float4*)&gr[128 + c4];
    float4 v;
    v.x = b.x / (1.f + expf(-a.x));
    v.y = b.y / (1.f + expf(-a.y));
    v.z = b.z / (1.f + expf(-a.z));
    v.w = b.w / (1.f + expf(-a.w));
    red_add_v4(&g_gv[gidx[n] * 128 + c4], v);
}

__global__ void gv2_k(const float* __restrict__ W, const float* __restrict__ b) {
    __shared__ float row[128];
    int r = blockIdx.x, d = threadIdx.x;
    row[d] = g_gv[r * 128 + d];
    __syncthreads();
    float acc = b[d];
    #pragma unroll 8
    for (int k = 0; k < 128; k++) acc = fmaf(row[k], W[k * 128 + d], acc);
    g_gv2[r * 128 + d] = acc;
}

__global__ void out_k(float* __restrict__ out) {
    __shared__ float sdata[128];
    int p = blockIdx.x, t = threadIdx.x;
    float dxy = g_gv2[(2 * p) * 128 + t] - g_gv2[(2 * p + 1) * 128 + t];
    sdata[t] = dxy * dxy;
    __syncthreads();
    for (int s = 64; s > 0; s >>= 1) {
        if (t < s) sdata[t] += sdata[t + s];
        __syncthreads();
    }
    if (t == 0) out[p] = -sdata[0];
}

// ---------------- host launch ----------------------------------------------
static void* sym(const void* s) { void* p = nullptr; cudaGetSymbolAddress(&p, s); return p; }

extern "C" void kernel_launch(void* const* d_in, const int* in_sizes, int n_in,
                              void* d_out, int out_size) {
    const float* nf     = (const float*)d_in[0];
    const float* ef     = (const float*)d_in[1];
    const int*   from   = (const int*)d_in[2];
    const int*   to     = (const int*)d_in[3];
    const int*   gidx   = (const int*)d_in[4];
    const float* enc_wn = (const float*)d_in[5];
    const float* enc_bn = (const float*)d_in[6];
    const float* enc_we = (const float*)d_in[7];
    const float* enc_be = (const float*)d_in[8];
    const float* msg_w1 = (const float*)d_in[9];
    const float* msg_b1 = (const float*)d_in[10];
    const float* msg_w2 = (const float*)d_in[11];
    const float* msg_b2 = (const float*)d_in[12];
    const float* rmsg_w1= (const float*)d_in[13];
    const float* rmsg_b1= (const float*)d_in[14];
    const float* rmsg_w2= (const float*)d_in[15];
    const float* rmsg_b2= (const float*)d_in[16];
    const float* upd_w1 = (const float*)d_in[17];
    const float* upd_b1 = (const float*)d_in[18];
    const float* upd_w2 = (const float*)d_in[19];
    const float* upd_b2 = (const float*)d_in[20];
    const float* agg_w1 = (const float*)d_in[21];
    const float* agg_b1 = (const float*)d_in[22];
    const float* agg_w2 = (const float*)d_in[23];
    const float* agg_b2 = (const float*)d_in[24];
    float* out = (float*)d_out;

    float* p_h    = (float*)sym(g_h);
    float* p_E    = (float*)sym(g_E);
    float* p_PQ   = (float*)sym(g_PQ);
    float* p_S    = (float*)sym(g_S);
    float* p_X    = (float*)sym(g_X);
    float* p_Hu   = (float*)sym(g_Hu);
    float* p_gv   = (float*)sym(g_gv);
    float* p_Wcat = (float*)sym(g_Wcat);
    float* p_WE   = (float*)sym(g_WE);
    float* p_c    = (float*)sym(g_c);
    int*   p_degt = (int*)sym(g_degt);
    int*   p_degf = (int*)sym(g_degf);
    __nv_bfloat16* p_Bh = (__nv_bfloat16*)sym(g_Bh);
    __nv_bfloat16* p_Bl = (__nv_bfloat16*)sym(g_Bl);

    const int GM = (N_NODES + 127) / 128;   // 235
    const int GE = (N_EDGES + 127) / 128;   // 2344
    #define SPT(W, off, K, N) spt_k<<<((K) * (N) + 255) / 256, 256>>>(W, p_Bh + (off), p_Bl + (off), K, N)

    // one-time prep
    fold_k<<<1, 512>>>(enc_we, enc_be, msg_w1, msg_b1, rmsg_w1, rmsg_b1);
    wcat_k<<<512, 256>>>(msg_w1, rmsg_w1);
    SPT(p_Wcat,  OFF_CAT, 128, 1024);
    SPT(msg_w2,  OFF_MW2, 256, 128);
    SPT(rmsg_w2, OFF_RW2, 256, 128);
    SPT(upd_w1,  OFF_UW1, 384, 256);
    SPT(upd_w2,  OFF_UW2, 256, 128);
    SPT(agg_w1,  OFF_AW1, 128, 256);
    SPT(enc_wn,  OFF_ENW, 32, 128);
    SPT(p_WE,    OFF_WET, 16, 512);
    zero_k<<<(N_NODES / 4 + 255) / 256, 256>>>((float4*)p_degt, N_NODES / 4);
    zero_k<<<(N_NODES / 4 + 255) / 256, 256>>>((float4*)p_degf, N_NODES / 4);
    hist_k<<<(N_EDGES + 255) / 256, 256>>>(from, to);

    // node encoder: h = nf @ enc_wn + enc_bn        [30000,32]@[32,128]
    tgemm_k<<<dim3(GM, 1), 256>>>(nf, 32, 32, p_Bh + OFF_ENW, p_Bl + OFF_ENW,
                                  enc_bn, nullptr, p_h, 128, N_NODES, 128, 0);
    // edge encoder (folded): E = ef @ WE + c        [300000,16]@[16,512]
    tgemm_k<<<dim3(GE, 4), 256>>>(ef, 16, 16, p_Bh + OFF_WET, p_Bl + OFF_WET,
                                  p_c, nullptr, p_E, 512, N_EDGES, 512, 0);

    for (int l = 0; l < NLAYERS; l++) {
        // PQ = h @ Wcat                             [30000,128]@[128,1024]
        tgemm_k<<<dim3(GM, 8), 256>>>(p_h, 128, 128, p_Bh + OFF_CAT, p_Bl + OFF_CAT,
                                      nullptr, nullptr, p_PQ, 1024, N_NODES, 1024, 0);
        zero_k<<<(N_NODES * 128 + 255) / 256, 256>>>((float4*)p_S, N_NODES * 128);
        edge_pass_k<<<N_EDGES / 8, 256>>>(from, to);
        // agg  = S[:,:256] @ msg_w2 + deg_to*msg_b2   -> X[:,0:128]
        tgemm_k<<<dim3(GM, 1), 256>>>(p_S, 512, 256, p_Bh + OFF_MW2, p_Bl + OFF_MW2,
                                      msg_b2, p_degt, p_X, 384, N_NODES, 128, 0);
        // ragg = S[:,256:] @ rmsg_w2 + deg_from*rmsg_b2 -> X[:,128:256]
        tgemm_k<<<dim3(GM, 1), 256>>>(p_S + 256, 512, 256, p_Bh + OFF_RW2, p_Bl + OFF_RW2,
                                      rmsg_b2, p_degf, p_X + 128, 384, N_NODES, 128, 0);
        copyh_k<<<(N_NODES * 32 + 255) / 256, 256>>>();
        // Hu = relu(X @ upd_w1 + b1)                [30000,384]@[384,256]
        tgemm_k<<<dim3(GM, 2), 256>>>(p_X, 384, 384, p_Bh + OFF_UW1, p_Bl + OFF_UW1,
                                      upd_b1, nullptr, p_Hu, 256, N_NODES, 256, FLAG_RELU);
        // h += Hu @ upd_w2 + b2                     [30000,256]@[256,128]
        tgemm_k<<<dim3(GM, 1), 256>>>(p_Hu, 256, 256, p_Bh + OFF_UW2, p_Bl + OFF_UW2,
                                      upd_b2, nullptr, p_h, 128, N_NODES, 128, FLAG_ADDC);
    }

    // g = h @ agg_w1 + b1                           [30000,128]@[128,256]
    tgemm_k<<<dim3(GM, 2), 256>>>(p_h, 128, 128, p_Bh + OFF_AW1, p_Bl + OFF_AW1,
                                  agg_b1, nullptr, p_Hu, 256, N_NODES, 256, 0);
    zero_k<<<(N_GRAPHS * 32 + 255) / 256, 256>>>((float4*)p_gv, N_GRAPHS * 32);
    gate_k<<<(N_NODES * 32 + 255) / 256, 256>>>(gidx);
    gv2_k<<<N_GRAPHS, 128>>>(agg_w2, agg_b2);
    out_k<<<128, 128>>>(out);
    (void)in_sizes; (void)n_in; (void)out_size;
}

// round 5
// speedup vs baseline: 1.5476x; 1.0387x over previous
#include <cuda_runtime.h>
#include <cuda_bf16.h>
#include <math.h>
#include <stdint.h>

#define N_NODES 30000
#define N_EDGES 300000
#define N_GRAPHS 256
#define DD 128
#define HH 256
#define NLAYERS 3

#define FLAG_RELU 1
#define FLAG_ADDC 2
#define FLAG_BIAS3 4

// ---------------- scratch -------------------------------------------------
__device__ float g_h[N_NODES * DD];
__device__ float g_E[(size_t)N_EDGES * 512];
__device__ float g_PQ[N_NODES * 1024];
__device__ float g_SH[(size_t)N_NODES * 640];    // [segsum_m(256)|segsum_r(256)|h(128)]
__device__ float g_Hu[N_NODES * HH];
__device__ float g_gv[N_GRAPHS * DD];
__device__ float g_gv2[N_GRAPHS * DD];
__device__ int   g_degt[N_NODES];
__device__ int   g_degf[N_NODES];
__device__ float g_WE[16 * 512];
__device__ float g_c[512];
__device__ float g_Wcat[128 * 1024];
__device__ float g_Vcat[640 * 256];              // fused [Vm;Vr;U1c]
__device__ float g_bias3[768];                   // [b1 | c1 | c2]

// bf16 hi/lo weight pool, [N][K] K-major (transposed)
#define OFF_CAT 0
#define OFF_UPD 131072
#define OFF_UW2 294912
#define OFF_AW1 327680
#define OFF_ENW 360448
#define OFF_WET 364544
#define BPOOL   372736
__device__ __nv_bfloat16 g_Bh[BPOOL];
__device__ __nv_bfloat16 g_Bl[BPOOL];

// ---------------- helpers ---------------------------------------------------
__device__ __forceinline__ void red_add_v4(float* addr, float4 v) {
    asm volatile("red.global.add.v4.f32 [%0], {%1,%2,%3,%4};"
                 :: "l"(addr), "f"(v.x), "f"(v.y), "f"(v.z), "f"(v.w) : "memory");
}
__device__ __forceinline__ uint32_t packlo2(float a, float b) {
    uint32_t r;
    asm("cvt.rn.bf16x2.f32 %0, %1, %2;" : "=r"(r) : "f"(b), "f"(a));
    return r;
}
__device__ __forceinline__ uint32_t smem_u32(const void* p) {
    uint32_t a;
    asm("{ .reg .u64 t; cvta.to.shared.u64 t, %1; cvt.u32.u64 %0, t; }" : "=r"(a) : "l"(p));
    return a;
}
__device__ __forceinline__ void mma16816(float* c, const uint32_t* a, const uint32_t* b) {
    asm("mma.sync.aligned.m16n8k16.row.col.f32.bf16.bf16.f32 "
        "{%0,%1,%2,%3}, {%4,%5,%6,%7}, {%8,%9}, {%0,%1,%2,%3};"
        : "+f"(c[0]), "+f"(c[1]), "+f"(c[2]), "+f"(c[3])
        : "r"(a[0]), "r"(a[1]), "r"(a[2]), "r"(a[3]), "r"(b[0]), "r"(b[1]));
}
#define LDSM4(r, addr)                                                         \
    asm volatile("ldmatrix.sync.aligned.m8n8.x4.shared.b16 {%0,%1,%2,%3}, [%4];" \
        : "=r"((r)[0]), "=r"((r)[1]), "=r"((r)[2]), "=r"((r)[3]) : "r"(addr))

__global__ void zero_k(float4* p, int n4) {
    int i = blockIdx.x * 256 + threadIdx.x;
    if (i < n4) p[i] = make_float4(0.f, 0.f, 0.f, 0.f);
}
__global__ void zeroS_k() {
    int idx = blockIdx.x * 256 + threadIdx.x;   // N_NODES*128 float4 (512 floats/node)
    if (idx >= N_NODES * 128) return;
    int n = idx >> 7, c = idx & 127;
    ((float4*)(g_SH + (size_t)n * 640))[c] = make_float4(0.f, 0.f, 0.f, 0.f);
}

// ---------------- warp-MMA split-bf16 GEMM ----------------------------------
// C[M,N] = [C +] relu( A[M,K](f32) @ B[N,K]^T + bias terms )
#define AST 20   // smem row stride in 32-bit words (16 payload + 4 pad)

__global__ void __launch_bounds__(256, 2) tgemm_k(
    const float* __restrict__ A, int lda, int K,
    const __nv_bfloat16* __restrict__ Bh, const __nv_bfloat16* __restrict__ Bl,
    const float* __restrict__ bias, const int* __restrict__ rs1,
    const int* __restrict__ rs2,
    float* __restrict__ C, int ldc, int M, int N, int flags)
{
    __shared__ uint32_t sAh[128 * AST], sAl[128 * AST];
    __shared__ uint32_t sBh[128 * AST], sBl[128 * AST];
    const int tid = threadIdx.x, wid = tid >> 5, lane = tid & 31;
    const int g = lane >> 2, t = lane & 3;
    const int m0 = blockIdx.x * 128, n0 = blockIdx.y * 128;
    const int mbase = (wid & 3) * 32, nbase = (wid >> 2) * 64;

    const uint32_t uAh = smem_u32(sAh), uAl = smem_u32(sAl);
    const uint32_t uBh = smem_u32(sBh), uBl = smem_u32(sBl);
    const uint32_t dAl = uAl - uAh, dBl = uBl - uBh;
    const int lrow = (lane & 7) + ((lane >> 3) & 1) * 8;   // ldmatrix row
    const int lcol = ((lane >> 4) & 1) * 4;                // ldmatrix word col

    float acc[2][8][4];
    #pragma unroll
    for (int i = 0; i < 2; i++)
        #pragma unroll
        for (int j = 0; j < 8; j++)
            #pragma unroll
            for (int q = 0; q < 4; q++) acc[i][j][q] = 0.f;

    const int arow = tid >> 1, ahalf = tid & 1;
    const bool mok = (m0 + arow) < M;
    const float* Ap = A + (size_t)(m0 + arow) * lda;
    const __nv_bfloat16* Bhp = Bh + (size_t)(n0 + arow) * K;
    const __nv_bfloat16* Blp = Bl + (size_t)(n0 + arow) * K;

    for (int k0 = 0; k0 < K; k0 += 32) {
        // ---- A: load f32, truncation-split to bf16 hi/lo, pack to smem ----
        {
            const bool kok = (k0 + ahalf * 16) < K;
            #pragma unroll
            for (int j = 0; j < 4; j++) {
                int c = ahalf * 16 + j * 4;
                float4 v = make_float4(0.f, 0.f, 0.f, 0.f);
                if (mok && kok) v = *(const float4*)(Ap + k0 + c);
                uint32_t x0 = __float_as_uint(v.x), x1 = __float_as_uint(v.y);
                uint32_t x2 = __float_as_uint(v.z), x3 = __float_as_uint(v.w);
                uint32_t hw0 = (x1 & 0xFFFF0000u) | (x0 >> 16);
                uint32_t hw1 = (x3 & 0xFFFF0000u) | (x2 >> 16);
                float l0 = v.x - __uint_as_float(x0 & 0xFFFF0000u);
                float l1 = v.y - __uint_as_float(x1 & 0xFFFF0000u);
                float l2 = v.z - __uint_as_float(x2 & 0xFFFF0000u);
                float l3 = v.w - __uint_as_float(x3 & 0xFFFF0000u);
                int w = arow * AST + (c >> 1);
                sAh[w] = hw0; sAh[w + 1] = hw1;
                sAl[w] = packlo2(l0, l1); sAl[w + 1] = packlo2(l2, l3);
            }
        }
        // ---- B: copy pre-split bf16 hi/lo to smem ----
        #pragma unroll
        for (int h2 = 0; h2 < 2; h2++) {
            int koff = ahalf * 16 + h2 * 8;
            int w = arow * AST + (koff >> 1);
            if (k0 + koff < K) {
                *(uint4*)&sBh[w] = *(const uint4*)(Bhp + k0 + koff);
                *(uint4*)&sBl[w] = *(const uint4*)(Blp + k0 + koff);
            } else {
                uint4 z = make_uint4(0, 0, 0, 0);
                *(uint4*)&sBh[w] = z;
                *(uint4*)&sBl[w] = z;
            }
        }
        __syncthreads();

        #pragma unroll
        for (int ks = 0; ks < 2; ks++) {
            uint32_t ah[2][4], al[2][4];
            #pragma unroll
            for (int i = 0; i < 2; i++) {
                uint32_t ad = uAh + (uint32_t)(((mbase + 16 * i + lrow) * AST + ks * 8 + lcol) * 4);
                LDSM4(ah[i], ad);
                LDSM4(al[i], ad + dAl);
            }
            #pragma unroll
            for (int jj = 0; jj < 4; jj++) {
                uint32_t bd = uBh + (uint32_t)(((nbase + 16 * jj + lrow) * AST + ks * 8 + lcol) * 4);
                uint32_t bh[4], bl[4];
                LDSM4(bh, bd);
                LDSM4(bl, bd + dBl);
                uint32_t b0[2] = { bh[0], bh[2] }, b1[2] = { bh[1], bh[3] };
                uint32_t c0[2] = { bl[0], bl[2] }, c1[2] = { bl[1], bl[3] };
                int j0 = 2 * jj, j1 = 2 * jj + 1;
                mma16816(acc[0][j0], ah[0], b0);
                mma16816(acc[1][j0], ah[1], b0);
                mma16816(acc[0][j1], ah[0], b1);
                mma16816(acc[1][j1], ah[1], b1);
                mma16816(acc[0][j0], al[0], b0);
                mma16816(acc[1][j0], al[1], b0);
                mma16816(acc[0][j1], al[0], b1);
                mma16816(acc[1][j1], al[1], b1);
                mma16816(acc[0][j0], ah[0], c0);
                mma16816(acc[1][j0], ah[1], c0);
                mma16816(acc[0][j1], ah[0], c1);
                mma16816(acc[1][j1], ah[1], c1);
            }
        }
        __syncthreads();
    }

    // ---- epilogue ----
    #pragma unroll
    for (int i = 0; i < 2; i++) {
        #pragma unroll
        for (int rr = 0; rr < 2; rr++) {
            int row = m0 + mbase + 16 * i + g + 8 * rr;
            if (row >= M) continue;
            float r1 = 0.f, r2 = 0.f;
            if (flags & FLAG_BIAS3) { r1 = (float)rs1[row]; r2 = (float)rs2[row]; }
            float* crow = C + (size_t)row * ldc;
            #pragma unroll
            for (int j = 0; j < 8; j++) {
                int nn = n0 + nbase + 8 * j + 2 * t;
                float2 v = make_float2(acc[i][j][2 * rr], acc[i][j][2 * rr + 1]);
                if (flags & FLAG_BIAS3) {
                    v.x += bias[nn] + r1 * bias[256 + nn] + r2 * bias[512 + nn];
                    v.y += bias[nn + 1] + r1 * bias[256 + nn + 1] + r2 * bias[512 + nn + 1];
                } else if (bias) {
                    v.x += bias[nn]; v.y += bias[nn + 1];
                }
                if (flags & FLAG_ADDC) {
                    float2 c0 = *(const float2*)(crow + nn);
                    v.x += c0.x; v.y += c0.y;
                }
                if (flags & FLAG_RELU) {
                    v.x = fmaxf(v.x, 0.f); v.y = fmaxf(v.y, 0.f);
                }
                *(float2*)(crow + nn) = v;
            }
        }
    }
}

// ---------------- prep kernels ---------------------------------------------
__global__ void spt_k(const float* __restrict__ W, __nv_bfloat16* __restrict__ oh,
                      __nv_bfloat16* __restrict__ ol, int K, int N) {
    int idx = blockIdx.x * 256 + threadIdx.x;
    if (idx >= K * N) return;
    int k = idx / N, n = idx % N;
    float v = W[idx];
    uint32_t xu = __float_as_uint(v);
    unsigned short hb = (unsigned short)(xu >> 16);
    float hf = __uint_as_float(xu & 0xFFFF0000u);
    __nv_bfloat16 l = __float2bfloat16(v - hf);
    union { unsigned short s; __nv_bfloat16 b; } u; u.s = hb;
    oh[(size_t)n * K + k] = u.b;
    ol[(size_t)n * K + k] = l;
}

__global__ void fold_k(const float* __restrict__ enc_we, const float* __restrict__ enc_be,
                       const float* __restrict__ mw1, const float* __restrict__ mb1,
                       const float* __restrict__ rw1, const float* __restrict__ rb1) {
    int j = threadIdx.x;
    const float* W1 = (j < 256) ? mw1 : rw1;
    const float* b1 = (j < 256) ? mb1 : rb1;
    int jc = j & 255;
    for (int k = 0; k < 16; k++) {
        float acc = 0.f;
        for (int d = 0; d < 128; d++)
            acc = fmaf(enc_we[k * 128 + d], W1[(256 + d) * 256 + jc], acc);
        g_WE[k * 512 + j] = acc;
    }
    float acc = b1[jc];
    for (int d = 0; d < 128; d++)
        acc = fmaf(enc_be[d], W1[(256 + d) * 256 + jc], acc);
    g_c[j] = acc;
}

__global__ void wcat_k(const float* __restrict__ mw1, const float* __restrict__ rw1) {
    int idx = blockIdx.x * 256 + threadIdx.x;
    if (idx >= 128 * 1024) return;
    int d = idx >> 10, c = idx & 1023;
    float v;
    if      (c < 256) v = mw1[d * 256 + c];
    else if (c < 512) v = mw1[(128 + d) * 256 + (c - 256)];
    else if (c < 768) v = rw1[d * 256 + (c - 512)];
    else              v = rw1[(128 + d) * 256 + (c - 768)];
    g_Wcat[idx] = v;
}

// Vcat[r][n], r<256: (mw2@U1a); r<512: (rmw2@U1b); else U1c. Plus bias3.
__global__ void vfold_k(const float* __restrict__ mw2, const float* __restrict__ rw2,
                        const float* __restrict__ uw1, const float* __restrict__ mb2,
                        const float* __restrict__ rmb2, const float* __restrict__ ub1) {
    int r = blockIdx.x, n = threadIdx.x;
    float acc = 0.f;
    if (r < 256) {
        for (int d = 0; d < 128; d++)
            acc = fmaf(mw2[r * 128 + d], uw1[d * 256 + n], acc);
    } else if (r < 512) {
        int k = r - 256;
        for (int d = 0; d < 128; d++)
            acc = fmaf(rw2[k * 128 + d], uw1[(128 + d) * 256 + n], acc);
    } else {
        acc = uw1[(256 + r - 512) * 256 + n];
    }
    g_Vcat[r * 256 + n] = acc;
    if (r == 0) {
        float c1 = 0.f, c2 = 0.f;
        for (int d = 0; d < 128; d++) {
            c1 = fmaf(mb2[d], uw1[d * 256 + n], c1);
            c2 = fmaf(rmb2[d], uw1[(128 + d) * 256 + n], c2);
        }
        g_bias3[n] = ub1[n];
        g_bias3[256 + n] = c1;
        g_bias3[512 + n] = c2;
    }
}

__global__ void hist_k(const int* __restrict__ from, const int* __restrict__ to) {
    int i = blockIdx.x * 256 + threadIdx.x;
    if (i >= N_EDGES) return;
    atomicAdd(&g_degt[to[i]], 1);
    atomicAdd(&g_degf[from[i]], 1);
}

// ---------------- per-edge elementwise pass ---------------------------------
__global__ void edge_pass_k(const int* __restrict__ from, const int* __restrict__ to) {
    int warp = (blockIdx.x * 256 + threadIdx.x) >> 5;
    int lane = threadIdx.x & 31;
    if (warp >= N_EDGES) return;
    int f = from[warp], t = to[warp];
    const float4* E4 = (const float4*)(g_E + (size_t)warp * 512);
    const float4* Pf = (const float4*)(g_PQ + (size_t)f * 1024);
    const float4* Pt = (const float4*)(g_PQ + (size_t)t * 1024);
    float* Sm = g_SH + (size_t)t * 640;
    float* Sr = g_SH + (size_t)f * 640 + 256;
    #pragma unroll
    for (int s = 0; s < 2; s++) {
        int c = lane + 32 * s;
        float4 e = E4[c], a = Pf[c], b = Pt[64 + c];
        float4 v;
        v.x = fmaxf(e.x + a.x + b.x, 0.f);
        v.y = fmaxf(e.y + a.y + b.y, 0.f);
        v.z = fmaxf(e.z + a.z + b.z, 0.f);
        v.w = fmaxf(e.w + a.w + b.w, 0.f);
        red_add_v4(Sm + 4 * c, v);
        float4 e2 = E4[64 + c], a2 = Pt[128 + c], b2 = Pf[192 + c];
        float4 v2;
        v2.x = fmaxf(e2.x + a2.x + b2.x, 0.f);
        v2.y = fmaxf(e2.y + a2.y + b2.y, 0.f);
        v2.z = fmaxf(e2.z + a2.z + b2.z, 0.f);
        v2.w = fmaxf(e2.w + a2.w + b2.w, 0.f);
        red_add_v4(Sr + 4 * c, v2);
    }
}

// copy h into SH[:, 512:640]
__global__ void copyh_k() {
    int idx = blockIdx.x * 256 + threadIdx.x;
    if (idx >= N_NODES * 32) return;
    int n = idx >> 5, c = idx & 31;
    ((float4*)(g_SH + (size_t)n * 640 + 512))[c] = ((const float4*)(g_h + (size_t)n * 128))[c];
}

__global__ void gate_k(const int* __restrict__ gidx) {
    int idx = blockIdx.x * 256 + threadIdx.x;
    if (idx >= N_NODES * 32) return;
    int n = idx >> 5, c4 = (idx & 31) * 4;
    const float* gr = g_Hu + (size_t)n * 256;
    float4 a = *(const float4*)&gr[c4];
    float4 b = *(const float4*)&gr[128 + c4];
    float4 v;
    v.x = b.x / (1.f + expf(-a.x));
    v.y = b.y / (1.f + expf(-a.y));
    v.z = b.z / (1.f + expf(-a.z));
    v.w = b.w / (1.f + expf(-a.w));
    red_add_v4(&g_gv[gidx[n] * 128 + c4], v);
}

__global__ void gv2_k(const float* __restrict__ W, const float* __restrict__ b) {
    __shared__ float row[128];
    int r = blockIdx.x, d = threadIdx.x;
    row[d] = g_gv[r * 128 + d];
    __syncthreads();
    float acc = b[d];
    #pragma unroll 8
    for (int k = 0; k < 128; k++) acc = fmaf(row[k], W[k * 128 + d], acc);
    g_gv2[r * 128 + d] = acc;
}

__global__ void out_k(float* __restrict__ out) {
    __shared__ float sdata[128];
    int p = blockIdx.x, t = threadIdx.x;
    float dxy = g_gv2[(2 * p) * 128 + t] - g_gv2[(2 * p + 1) * 128 + t];
    sdata[t] = dxy * dxy;
    __syncthreads();
    for (int s = 64; s > 0; s >>= 1) {
        if (t < s) sdata[t] += sdata[t + s];
        __syncthreads();
    }
    if (t == 0) out[p] = -sdata[0];
}

// ---------------- host launch ----------------------------------------------
static void* sym(const void* s) { void* p = nullptr; cudaGetSymbolAddress(&p, s); return p; }

extern "C" void kernel_launch(void* const* d_in, const int* in_sizes, int n_in,
                              void* d_out, int out_size) {
    const float* nf     = (const float*)d_in[0];
    const float* ef     = (const float*)d_in[1];
    const int*   from   = (const int*)d_in[2];
    const int*   to     = (const int*)d_in[3];
    const int*   gidx   = (const int*)d_in[4];
    const float* enc_wn = (const float*)d_in[5];
    const float* enc_bn = (const float*)d_in[6];
    const float* enc_we = (const float*)d_in[7];
    const float* enc_be = (const float*)d_in[8];
    const float* msg_w1 = (const float*)d_in[9];
    const float* msg_b1 = (const float*)d_in[10];
    const float* msg_w2 = (const float*)d_in[11];
    const float* msg_b2 = (const float*)d_in[12];
    const float* rmsg_w1= (const float*)d_in[13];
    const float* rmsg_b1= (const float*)d_in[14];
    const float* rmsg_w2= (const float*)d_in[15];
    const float* rmsg_b2= (const float*)d_in[16];
    const float* upd_w1 = (const float*)d_in[17];
    const float* upd_b1 = (const float*)d_in[18];
    const float* upd_w2 = (const float*)d_in[19];
    const float* upd_b2 = (const float*)d_in[20];
    const float* agg_w1 = (const float*)d_in[21];
    const float* agg_b1 = (const float*)d_in[22];
    const float* agg_w2 = (const float*)d_in[23];
    const float* agg_b2 = (const float*)d_in[24];
    float* out = (float*)d_out;

    float* p_h    = (float*)sym(g_h);
    float* p_E    = (float*)sym(g_E);
    float* p_PQ   = (float*)sym(g_PQ);
    float* p_SH   = (float*)sym(g_SH);
    float* p_Hu   = (float*)sym(g_Hu);
    float* p_gv   = (float*)sym(g_gv);
    float* p_Wcat = (float*)sym(g_Wcat);
    float* p_Vcat = (float*)sym(g_Vcat);
    float* p_b3   = (float*)sym(g_bias3);
    float* p_WE   = (float*)sym(g_WE);
    float* p_c    = (float*)sym(g_c);
    int*   p_degt = (int*)sym(g_degt);
    int*   p_degf = (int*)sym(g_degf);
    __nv_bfloat16* p_Bh = (__nv_bfloat16*)sym(g_Bh);
    __nv_bfloat16* p_Bl = (__nv_bfloat16*)sym(g_Bl);

    const int GM = (N_NODES + 127) / 128;   // 235
    const int GE = (N_EDGES + 127) / 128;   // 2344
    #define SPT(W, off, K, N) spt_k<<<((K) * (N) + 255) / 256, 256>>>(W, p_Bh + (off), p_Bl + (off), K, N)

    // one-time prep
    fold_k<<<1, 512>>>(enc_we, enc_be, msg_w1, msg_b1, rmsg_w1, rmsg_b1);
    wcat_k<<<512, 256>>>(msg_w1, rmsg_w1);
    vfold_k<<<640, 256>>>(msg_w2, rmsg_w2, upd_w1, msg_b2, rmsg_b2, upd_b1);
    SPT(p_Wcat,  OFF_CAT, 128, 1024);
    SPT(p_Vcat,  OFF_UPD, 640, 256);
    SPT(upd_w2,  OFF_UW2, 256, 128);
    SPT(agg_w1,  OFF_AW1, 128, 256);
    SPT(enc_wn,  OFF_ENW, 32, 128);
    SPT(p_WE,    OFF_WET, 16, 512);
    zero_k<<<(N_NODES / 4 + 255) / 256, 256>>>((float4*)p_degt, N_NODES / 4);
    zero_k<<<(N_NODES / 4 + 255) / 256, 256>>>((float4*)p_degf, N_NODES / 4);
    hist_k<<<(N_EDGES + 255) / 256, 256>>>(from, to);

    // node encoder: h = nf @ enc_wn + enc_bn        [30000,32]@[32,128]
    tgemm_k<<<dim3(GM, 1), 256>>>(nf, 32, 32, p_Bh + OFF_ENW, p_Bl + OFF_ENW,
                                  enc_bn, nullptr, nullptr, p_h, 128, N_NODES, 128, 0);
    // edge encoder (folded): E = ef @ WE + c        [300000,16]@[16,512]
    tgemm_k<<<dim3(GE, 4), 256>>>(ef, 16, 16, p_Bh + OFF_WET, p_Bl + OFF_WET,
                                  p_c, nullptr, nullptr, p_E, 512, N_EDGES, 512, 0);

    for (int l = 0; l < NLAYERS; l++) {
        // PQ = h @ Wcat                             [30000,128]@[128,1024]
        tgemm_k<<<dim3(GM, 8), 256>>>(p_h, 128, 128, p_Bh + OFF_CAT, p_Bl + OFF_CAT,
                                      nullptr, nullptr, nullptr, p_PQ, 1024, N_NODES, 1024, 0);
        zeroS_k<<<(N_NODES * 128 + 255) / 256, 256>>>();
        copyh_k<<<(N_NODES * 32 + 255) / 256, 256>>>();
        edge_pass_k<<<N_EDGES / 8, 256>>>(from, to);
        // Hu = relu(SH @ Vcat + b1 + deg_t*c1 + deg_f*c2)   [30000,640]@[640,256]
        tgemm_k<<<dim3(GM, 2), 256>>>(p_SH, 640, 640, p_Bh + OFF_UPD, p_Bl + OFF_UPD,
                                      p_b3, p_degt, p_degf, p_Hu, 256, N_NODES, 256,
                                      FLAG_RELU | FLAG_BIAS3);
        // h += Hu @ upd_w2 + b2                     [30000,256]@[256,128]
        tgemm_k<<<dim3(GM, 1), 256>>>(p_Hu, 256, 256, p_Bh + OFF_UW2, p_Bl + OFF_UW2,
                                      upd_b2, nullptr, nullptr, p_h, 128, N_NODES, 128, FLAG_ADDC);
    }

    // g = h @ agg_w1 + b1                           [30000,128]@[128,256]
    tgemm_k<<<dim3(GM, 2), 256>>>(p_h, 128, 128, p_Bh + OFF_AW1, p_Bl + OFF_AW1,
                                  agg_b1, nullptr, nullptr, p_Hu, 256, N_NODES, 256, 0);
    zero_k<<<(N_GRAPHS * 32 + 255) / 256, 256>>>((float4*)p_gv, N_GRAPHS * 32);
    gate_k<<<(N_NODES * 32 + 255) / 256, 256>>>(gidx);
    gv2_k<<<N_GRAPHS, 128>>>(agg_w2, agg_b2);
    out_k<<<128, 128>>>(out);
    (void)in_sizes; (void)n_in; (void)out_size;
}